// round 2
// baseline (speedup 1.0000x reference)
#include <cuda_runtime.h>

#define H 4
#define KCODES 8192
#define DFULL 1024
#define DHEAD 256
#define BATCH 8192

#define BM 128
#define BN 128
#define BK 8
#define TM 8
#define TN 8

// Scratch (no allocations allowed)
__device__ unsigned long long g_min[BATCH * H];
__device__ float g_e2[H * KCODES];

// Packed f32x2 helpers (Blackwell dual-pumped FP32 pipe)
#define FMA_F32X2(d, a, b, c) \
    asm("fma.rn.f32x2 %0, %1, %2, %3;" : "=l"(d) : "l"(a), "l"(b), "l"(c))
#define PACK_F32X2(out, lo, hi) \
    asm("mov.b64 %0, {%1, %2};" : "=l"(out) : "r"(lo), "r"(hi))
#define UNPACK_F32X2(lo, hi, in) \
    asm("mov.b64 {%0, %1}, %2;" : "=r"(lo), "=r"(hi) : "l"(in))

// ---------------------------------------------------------------------------
// Reset packed (dist,code) mins
// ---------------------------------------------------------------------------
__global__ void reset_kernel() {
    int i = blockIdx.x * blockDim.x + threadIdx.x;
    if (i < BATCH * H) g_min[i] = 0xFFFFFFFFFFFFFFFFull;
}

// ---------------------------------------------------------------------------
// e2[h,k] = sum_d codebooks[h,k,d]^2   (warp per code row)
// ---------------------------------------------------------------------------
__global__ void e2_kernel(const float* __restrict__ cb) {
    int warp = (blockIdx.x * blockDim.x + threadIdx.x) >> 5;
    int lane = threadIdx.x & 31;
    if (warp >= H * KCODES) return;
    const float* p = cb + (size_t)warp * DHEAD;
    float s = 0.f;
#pragma unroll
    for (int i = 0; i < DHEAD; i += 32) {
        float v = p[i + lane];
        s = fmaf(v, v, s);
    }
#pragma unroll
    for (int o = 16; o; o >>= 1) s += __shfl_xor_sync(0xFFFFFFFFu, s, o);
    if (lane == 0) g_e2[warp] = s;
}

// ---------------------------------------------------------------------------
// Fused GEMM (x . e^T) + argmin over k of (e2 - 2*xe).
// Block: 128 b-rows x 128 k-cols, 256 threads, 8x8 microtile, BK=8 k-depth.
// Inner product uses packed fma.rn.f32x2 (2 FMA lanes per instruction).
// ---------------------------------------------------------------------------
__device__ __forceinline__ unsigned float_key(float f) {
    unsigned ub = __float_as_uint(f);
    return (ub & 0x80000000u) ? ~ub : (ub | 0x80000000u);
}

__global__ __launch_bounds__(256, 2)
void dist_argmin_kernel(const float* __restrict__ x, const float* __restrict__ cb) {
    __shared__ __align__(16) float Xs[BK][BM];
    __shared__ __align__(16) float Es[BK][BN];
    __shared__ unsigned long long red[BM][17];

    const int h  = blockIdx.z;
    const int bi = blockIdx.x * BM;
    const int kj = blockIdx.y * BN;
    const int tid = threadIdx.x;
    const int tx = tid & 15, ty = tid >> 4;

    const float* xg = x  + (size_t)bi * DFULL + (size_t)h * DHEAD;       // row stride DFULL
    const float* eg = cb + ((size_t)h * KCODES + kj) * DHEAD;            // row stride DHEAD

    const int lrow = tid >> 1;        // 0..127
    const int lcol = (tid & 1) * 4;   // 0 or 4

    // acc[m][np] holds distances for n = 2*np, 2*np+1 packed as f32x2
    unsigned long long acc[TM][TN / 2];
#pragma unroll
    for (int m = 0; m < TM; m++)
#pragma unroll
        for (int n = 0; n < TN / 2; n++) acc[m][n] = 0ull;

    for (int kk = 0; kk < DHEAD; kk += BK) {
        float4 xv = *(const float4*)(xg + (size_t)lrow * DFULL + kk + lcol);
        float4 ev = *(const float4*)(eg + (size_t)lrow * DHEAD + kk + lcol);

        Xs[lcol + 0][lrow] = xv.x; Xs[lcol + 1][lrow] = xv.y;
        Xs[lcol + 2][lrow] = xv.z; Xs[lcol + 3][lrow] = xv.w;
        Es[lcol + 0][lrow] = ev.x; Es[lcol + 1][lrow] = ev.y;
        Es[lcol + 2][lrow] = ev.z; Es[lcol + 3][lrow] = ev.w;
        __syncthreads();

#pragma unroll
        for (int c = 0; c < BK; c++) {
            float rm[TM];
            *(float4*)&rm[0] = *(const float4*)&Xs[c][ty * TM];
            *(float4*)&rm[4] = *(const float4*)&Xs[c][ty * TM + 4];

            unsigned long long rmp[TM];
#pragma unroll
            for (int m = 0; m < TM; m++) {
                unsigned rb = __float_as_uint(rm[m]);
                PACK_F32X2(rmp[m], rb, rb);
            }

            ulonglong2 e0 = *(const ulonglong2*)&Es[c][tx * TN];
            ulonglong2 e1 = *(const ulonglong2*)&Es[c][tx * TN + 4];
            unsigned long long rnp[4];
            rnp[0] = e0.x; rnp[1] = e0.y; rnp[2] = e1.x; rnp[3] = e1.y;

#pragma unroll
            for (int m = 0; m < TM; m++)
#pragma unroll
                for (int n = 0; n < TN / 2; n++)
                    FMA_F32X2(acc[m][n], rmp[m], rnp[n], acc[m][n]);
        }
        __syncthreads();
    }

    // Epilogue: per-row min of packed (e2 - 2*xe, code)
    float e2c[TN];
#pragma unroll
    for (int n = 0; n < TN; n++)
        e2c[n] = g_e2[h * KCODES + kj + tx * TN + n];

#pragma unroll
    for (int m = 0; m < TM; m++) {
        unsigned long long best = 0xFFFFFFFFFFFFFFFFull;
#pragma unroll
        for (int np = 0; np < TN / 2; np++) {
            unsigned lo_b, hi_b;
            UNPACK_F32X2(lo_b, hi_b, acc[m][np]);
            float a0 = __uint_as_float(lo_b);
            float a1 = __uint_as_float(hi_b);
            float mv0 = fmaf(-2.f, a0, e2c[2 * np]);
            float mv1 = fmaf(-2.f, a1, e2c[2 * np + 1]);
            unsigned long long key0 =
                ((unsigned long long)float_key(mv0) << 32) |
                (unsigned)(kj + tx * TN + 2 * np);
            unsigned long long key1 =
                ((unsigned long long)float_key(mv1) << 32) |
                (unsigned)(kj + tx * TN + 2 * np + 1);
            best = (key0 < best) ? key0 : best;
            best = (key1 < best) ? key1 : best;
        }
        red[ty * TM + m][tx] = best;
    }
    __syncthreads();

    if (tid < BM) {
        unsigned long long best = red[tid][0];
#pragma unroll
        for (int i = 1; i < 16; i++) {
            unsigned long long v = red[tid][i];
            best = (v < best) ? v : best;
        }
        atomicMin(&g_min[(size_t)(bi + tid) * H + h], best);
    }
}

// ---------------------------------------------------------------------------
// Finalize: gather q, write quantized/codes, loss = 0.25 * sum_h mean((q-x)^2)
// ---------------------------------------------------------------------------
__global__ void finalize_kernel(const float* __restrict__ x, const float* __restrict__ cb,
                                float* __restrict__ loss, float* __restrict__ quant,
                                float* __restrict__ codes_out) {
    const int b = blockIdx.x;
    const int tid = threadIdx.x;  // 256 threads, one per head-dim element
    __shared__ float sred[256];

    float partial = 0.f;
#pragma unroll
    for (int h = 0; h < H; h++) {
        unsigned long long packed = g_min[(size_t)b * H + h];
        unsigned code = (unsigned)(packed & 0xFFFFFFFFu);
        if (tid == 0) codes_out[(size_t)b * H + h] = (float)code;
        float qv = cb[((size_t)h * KCODES + code) * DHEAD + tid];
        float xv = x[(size_t)b * DFULL + (size_t)h * DHEAD + tid];
        quant[(size_t)b * DFULL + (size_t)h * DHEAD + tid] = qv;
        float d = qv - xv;
        partial = fmaf(d, d, partial);
    }
    sred[tid] = partial;
    __syncthreads();
#pragma unroll
    for (int s = 128; s > 0; s >>= 1) {
        if (tid < s) sred[tid] += sred[tid + s];
        __syncthreads();
    }
    if (tid == 0) loss[b] = 0.25f * sred[0] * (1.0f / (float)DHEAD);
}

// ---------------------------------------------------------------------------
extern "C" void kernel_launch(void* const* d_in, const int* in_sizes, int n_in,
                              void* d_out, int out_size) {
    const float* x  = (const float*)d_in[0];   // inputs   (B,1,D)
    const float* cb = (const float*)d_in[1];   // codebooks (H,K,d)
    float* out = (float*)d_out;

    float* loss  = out;
    float* quant = out + BATCH;
    float* codes = out + BATCH + (size_t)BATCH * DFULL;

    reset_kernel<<<(BATCH * H + 255) / 256, 256>>>();
    e2_kernel<<<(H * KCODES) / 8, 256>>>(cb);

    dim3 grid(BATCH / BM, KCODES / BN, H);
    dist_argmin_kernel<<<grid, 256>>>(x, cb);

    finalize_kernel<<<BATCH, 256>>>(x, cb, loss, quant, codes);
}

// round 4
// speedup vs baseline: 1.4040x; 1.4040x over previous
#include <cuda_runtime.h>
#include <cstdint>

#define H 4
#define KCODES 8192
#define DFULL 1024
#define DHEAD 256
#define BATCH 8192

#define TILE_M 128
#define TILE_N 128
#define KC 16
#define NCHUNK (DHEAD / KC)   // 16
#define LDA 20                // padded smem stride (floats): conflict-free

// Scratch
__device__ unsigned long long g_min[BATCH * H];
__device__ float g_e2[H * KCODES];

__device__ __forceinline__ float tf32_rn(float v) {
    uint32_t r;
    asm("cvt.rn.tf32.f32 %0, %1;" : "=r"(r) : "f"(v));
    return __uint_as_float(r);
}
__device__ __forceinline__ uint32_t float_key(float f) {
    unsigned ub = __float_as_uint(f);
    return (ub & 0x80000000u) ? ~ub : (ub | 0x80000000u);
}

#define MMA_TF32(c, a, b0, b1) \
    asm volatile("mma.sync.aligned.m16n8k8.row.col.f32.tf32.tf32.f32 " \
        "{%0,%1,%2,%3}, {%4,%5,%6,%7}, {%8,%9}, {%0,%1,%2,%3};" \
        : "+f"((c)[0]), "+f"((c)[1]), "+f"((c)[2]), "+f"((c)[3]) \
        : "r"((a)[0]), "r"((a)[1]), "r"((a)[2]), "r"((a)[3]), \
          "r"(b0), "r"(b1))

// ---------------------------------------------------------------------------
__global__ void reset_kernel() {
    int i = blockIdx.x * blockDim.x + threadIdx.x;
    if (i < BATCH * H) g_min[i] = 0xFFFFFFFFFFFFFFFFull;
}

__global__ void e2_kernel(const float* __restrict__ cb) {
    int warp = (blockIdx.x * blockDim.x + threadIdx.x) >> 5;
    int lane = threadIdx.x & 31;
    if (warp >= H * KCODES) return;
    const float* p = cb + (size_t)warp * DHEAD;
    float s = 0.f;
#pragma unroll
    for (int i = 0; i < DHEAD; i += 32) {
        float v = p[i + lane];
        s = fmaf(v, v, s);
    }
#pragma unroll
    for (int o = 16; o; o >>= 1) s += __shfl_xor_sync(0xFFFFFFFFu, s, o);
    if (lane == 0) g_e2[warp] = s;
}

// ---------------------------------------------------------------------------
// Split-precision TF32 mma.sync GEMM + fused argmin.
// grid (BATCH/128, KCODES/128, H), 256 threads (8 warps: 2 M x 4 N).
// ---------------------------------------------------------------------------
__global__ __launch_bounds__(256, 2)
void dist_argmin_kernel(const float* __restrict__ x, const float* __restrict__ cb) {
    __shared__ float As_hi[TILE_M * LDA];
    __shared__ float As_lo[TILE_M * LDA];
    __shared__ float Bs_hi[TILE_N * LDA];
    __shared__ float Bs_lo[TILE_N * LDA];
    __shared__ float e2s[TILE_N];
    __shared__ unsigned long long red[TILE_M][4];

    const int tid = threadIdx.x;
    const int lane = tid & 31;
    const int wid = tid >> 5;
    const int warp_m = wid & 1;         // 2 warps along M
    const int warp_n = wid >> 1;        // 4 warps along N
    const int g  = lane >> 2;           // 0..7
    const int t4 = lane & 3;            // 0..3

    const int h  = blockIdx.z;
    const int bi = blockIdx.x * TILE_M;
    const int kj = blockIdx.y * TILE_N;

    if (tid < TILE_N) e2s[tid] = g_e2[h * KCODES + kj + tid];

    const float* xg = x  + (size_t)bi * DFULL + (size_t)h * DHEAD;
    const float* eg = cb + ((size_t)h * KCODES + kj) * DHEAD;

    float acc[4][4][4];
#pragma unroll
    for (int mt = 0; mt < 4; mt++)
#pragma unroll
        for (int nt = 0; nt < 4; nt++)
#pragma unroll
            for (int r = 0; r < 4; r++) acc[mt][nt][r] = 0.f;

#pragma unroll 1
    for (int ck = 0; ck < NCHUNK; ck++) {
        // ---- global prefetch: 2 float4 per thread for A and B ----
        float4 av[2], bv[2];
#pragma unroll
        for (int i = 0; i < 2; i++) {
            int idx = tid + 256 * i;
            int r = idx >> 2, c4 = idx & 3;
            av[i] = *(const float4*)(xg + (size_t)r * DFULL + ck * KC + c4 * 4);
            bv[i] = *(const float4*)(eg + (size_t)r * DHEAD + ck * KC + c4 * 4);
        }
        __syncthreads();   // previous chunk's compute done -> smem free

        // ---- split hi/lo (tf32-rounded) and store ----
#pragma unroll
        for (int i = 0; i < 2; i++) {
            int idx = tid + 256 * i;
            int r = idx >> 2, c4 = idx & 3;
            int off = r * LDA + c4 * 4;
            float4 hi, lo;
            hi.x = tf32_rn(av[i].x); lo.x = tf32_rn(av[i].x - hi.x);
            hi.y = tf32_rn(av[i].y); lo.y = tf32_rn(av[i].y - hi.y);
            hi.z = tf32_rn(av[i].z); lo.z = tf32_rn(av[i].z - hi.z);
            hi.w = tf32_rn(av[i].w); lo.w = tf32_rn(av[i].w - hi.w);
            *(float4*)&As_hi[off] = hi;
            *(float4*)&As_lo[off] = lo;
            hi.x = tf32_rn(bv[i].x); lo.x = tf32_rn(bv[i].x - hi.x);
            hi.y = tf32_rn(bv[i].y); lo.y = tf32_rn(bv[i].y - hi.y);
            hi.z = tf32_rn(bv[i].z); lo.z = tf32_rn(bv[i].z - hi.z);
            hi.w = tf32_rn(bv[i].w); lo.w = tf32_rn(bv[i].w - hi.w);
            *(float4*)&Bs_hi[off] = hi;
            *(float4*)&Bs_lo[off] = lo;
        }
        __syncthreads();

        // ---- compute: 2 k-steps of 8 ----
#pragma unroll
        for (int ks = 0; ks < 2; ks++) {
            const int k0 = ks * 8;
            uint32_t ah[4][4], al[4][4];
#pragma unroll
            for (int mt = 0; mt < 4; mt++) {
                int m0 = (warp_m * 64 + mt * 16 + g) * LDA + k0 + t4;
                int m1 = m0 + 8 * LDA;
                ah[mt][0] = __float_as_uint(As_hi[m0]);
                ah[mt][1] = __float_as_uint(As_hi[m1]);
                ah[mt][2] = __float_as_uint(As_hi[m0 + 4]);
                ah[mt][3] = __float_as_uint(As_hi[m1 + 4]);
                al[mt][0] = __float_as_uint(As_lo[m0]);
                al[mt][1] = __float_as_uint(As_lo[m1]);
                al[mt][2] = __float_as_uint(As_lo[m0 + 4]);
                al[mt][3] = __float_as_uint(As_lo[m1 + 4]);
            }
#pragma unroll
            for (int nt = 0; nt < 4; nt++) {
                int n0 = (warp_n * 32 + nt * 8 + g) * LDA + k0 + t4;
                uint32_t bh0 = __float_as_uint(Bs_hi[n0]);
                uint32_t bh1 = __float_as_uint(Bs_hi[n0 + 4]);
                uint32_t bl0 = __float_as_uint(Bs_lo[n0]);
                uint32_t bl1 = __float_as_uint(Bs_lo[n0 + 4]);
#pragma unroll
                for (int mt = 0; mt < 4; mt++) {
                    MMA_TF32(acc[mt][nt], ah[mt], bh0, bh1);
                    MMA_TF32(acc[mt][nt], ah[mt], bl0, bl1);
                    MMA_TF32(acc[mt][nt], al[mt], bh0, bh1);
                }
            }
        }
    }

    // ---- epilogue: dist = e2 - 2*acc; per-row packed argmin ----
#pragma unroll
    for (int mt = 0; mt < 4; mt++) {
        int r0 = warp_m * 64 + mt * 16 + g;
        int r1 = r0 + 8;
        unsigned long long b0 = 0xFFFFFFFFFFFFFFFFull;
        unsigned long long b1 = 0xFFFFFFFFFFFFFFFFull;
#pragma unroll
        for (int nt = 0; nt < 4; nt++) {
            int c0 = warp_n * 32 + nt * 8 + 2 * t4;
            float d00 = fmaf(-2.f, acc[mt][nt][0], e2s[c0]);
            float d01 = fmaf(-2.f, acc[mt][nt][1], e2s[c0 + 1]);
            float d10 = fmaf(-2.f, acc[mt][nt][2], e2s[c0]);
            float d11 = fmaf(-2.f, acc[mt][nt][3], e2s[c0 + 1]);
            unsigned long long k00 = ((unsigned long long)float_key(d00) << 32) | (unsigned)(kj + c0);
            unsigned long long k01 = ((unsigned long long)float_key(d01) << 32) | (unsigned)(kj + c0 + 1);
            unsigned long long k10 = ((unsigned long long)float_key(d10) << 32) | (unsigned)(kj + c0);
            unsigned long long k11 = ((unsigned long long)float_key(d11) << 32) | (unsigned)(kj + c0 + 1);
            b0 = (k00 < b0) ? k00 : b0;  b0 = (k01 < b0) ? k01 : b0;
            b1 = (k10 < b1) ? k10 : b1;  b1 = (k11 < b1) ? k11 : b1;
        }
        // reduce across the 4 threads (t4) sharing each row
        unsigned long long o;
        o = __shfl_xor_sync(0xFFFFFFFFu, b0, 1); b0 = (o < b0) ? o : b0;
        o = __shfl_xor_sync(0xFFFFFFFFu, b0, 2); b0 = (o < b0) ? o : b0;
        o = __shfl_xor_sync(0xFFFFFFFFu, b1, 1); b1 = (o < b1) ? o : b1;
        o = __shfl_xor_sync(0xFFFFFFFFu, b1, 2); b1 = (o < b1) ? o : b1;
        if (t4 == 0) {
            red[r0][warp_n] = b0;
            red[r1][warp_n] = b1;
        }
    }
    __syncthreads();

    if (tid < TILE_M) {
        unsigned long long best = red[tid][0];
#pragma unroll
        for (int i = 1; i < 4; i++) {
            unsigned long long v = red[tid][i];
            best = (v < best) ? v : best;
        }
        atomicMin(&g_min[(size_t)(bi + tid) * H + h], best);
    }
}

// ---------------------------------------------------------------------------
__global__ void finalize_kernel(const float* __restrict__ x, const float* __restrict__ cb,
                                float* __restrict__ loss, float* __restrict__ quant,
                                float* __restrict__ codes_out) {
    const int b = blockIdx.x;
    const int tid = threadIdx.x;
    __shared__ float sred[256];

    float partial = 0.f;
#pragma unroll
    for (int h = 0; h < H; h++) {
        unsigned long long packed = g_min[(size_t)b * H + h];
        unsigned code = (unsigned)(packed & 0xFFFFFFFFu);
        if (tid == 0) codes_out[(size_t)b * H + h] = (float)code;
        float qv = cb[((size_t)h * KCODES + code) * DHEAD + tid];
        float xv = x[(size_t)b * DFULL + (size_t)h * DHEAD + tid];
        quant[(size_t)b * DFULL + (size_t)h * DHEAD + tid] = qv;
        float d = qv - xv;
        partial = fmaf(d, d, partial);
    }
    sred[tid] = partial;
    __syncthreads();
#pragma unroll
    for (int s = 128; s > 0; s >>= 1) {
        if (tid < s) sred[tid] += sred[tid + s];
        __syncthreads();
    }
    if (tid == 0) loss[b] = 0.25f * sred[0] * (1.0f / (float)DHEAD);
}

// ---------------------------------------------------------------------------
extern "C" void kernel_launch(void* const* d_in, const int* in_sizes, int n_in,
                              void* d_out, int out_size) {
    const float* x  = (const float*)d_in[0];
    const float* cb = (const float*)d_in[1];
    float* out = (float*)d_out;

    float* loss  = out;
    float* quant = out + BATCH;
    float* codes = out + BATCH + (size_t)BATCH * DFULL;

    reset_kernel<<<(BATCH * H + 255) / 256, 256>>>();
    e2_kernel<<<(H * KCODES) / 8, 256>>>(cb);

    dim3 grid(BATCH / TILE_M, KCODES / TILE_N, H);
    dist_argmin_kernel<<<grid, 256>>>(x, cb);

    finalize_kernel<<<BATCH, 256>>>(x, cb, loss, quant, codes);
}